// round 6
// baseline (speedup 1.0000x reference)
#include <cuda_runtime.h>
#include <cstdint>

// Output (f32 elements): [ uniq as float 0..N-1 | msg rows f32 [N,D] ]
//   out_size = N*(D+1) = 25,700,000  (D=256, N=100,000)
// (Fallback: out_size % (D+2)==0 -> int64 uniq layout.)
// Per-node best key (u64: t_bits<<32 | event_pos) lives in the FIRST 8 BYTES of
// output row n during scatter; the owning gather warp reads it, then overwrites
// the row. Row base bytes = 4*base + 1024*n -> 16B aligned.

__device__ __forceinline__ unsigned long long*
key_slot(float* out, long long base, int D, int n) {
    return (unsigned long long*)(out + base + (size_t)n * (size_t)D);
}

__global__ void init_keys_kernel(float* __restrict__ out, long long base,
                                 int N, int D) {
    int n = blockIdx.x * blockDim.x + threadIdx.x;
    if (n < N) *key_slot(out, base, D, n) = 0ULL;
}

// pA/pB: one is index ([E] int32 OR int64), the other t (f32 [E]).
// index[:N] = arange(N) guarantee: index u32 words are tiny; uniform-[0,1)
// float bit patterns (~0x3F000000) are huge.
__global__ void scatter_max_kernel(const void* __restrict__ pA,
                                   const void* __restrict__ pB,
                                   float* __restrict__ out,
                                   long long base, int E, int N, int D) {
    const unsigned int* A32 = (const unsigned int*)pA;
    unsigned int nn = (unsigned int)N;
    bool a_is_index = (A32[0] < nn) && (A32[2] < nn);
    const void* idxp = a_is_index ? pA : pB;
    const float* __restrict__ t =
        a_is_index ? (const float*)pB : (const float*)pA;

    // int64 index: odd u32 words (high halves of arange prefix) are 0.
    // int32 index: odd u32 words are index[1],index[3],index[5] = 1,3,5.
    const unsigned int* I32 = (const unsigned int*)idxp;
    bool idx_is_i64 = (I32[1] == 0u) && (I32[3] == 0u) && (I32[5] == 0u);

    int i = blockIdx.x * blockDim.x + threadIdx.x;
    if (i < E) {
        int id = idx_is_i64 ? (int)((const long long*)idxp)[i]
                            : ((const int*)idxp)[i];
        if ((unsigned int)id < nn) {   // guard: never touch wild addresses
            unsigned long long key =
                ((unsigned long long)__float_as_uint(t[i]) << 32) | (unsigned int)i;
            atomicMax(key_slot(out, base, D, id), key);
        }
    }
}

// One warp per node row; 4 warps per block.
__global__ void gather_kernel(const float* __restrict__ msg,
                              float* __restrict__ out,
                              long long base, int N, int D, int E, int uniq_i64) {
    int n = blockIdx.x * 4 + (threadIdx.x >> 5);
    if (n >= N) return;
    int lane = threadIdx.x & 31;

    unsigned long long key = *key_slot(out, base, D, n);   // broadcast load
    unsigned int pos = (unsigned int)(key & 0xFFFFFFFFULL);
    if (pos >= (unsigned int)E) pos = 0;   // guard (impossible if scatter ran)
    __syncwarp();  // all lanes read the key before the row is overwritten

    if (lane == 0) {
        if (uniq_i64) ((long long*)out)[n] = (long long)n;
        else          out[n] = (float)n;   // uniq as FLOAT values (exact < 2^24)
    }

    const float4* __restrict__ src =
        (const float4*)(msg + (size_t)pos * (size_t)D);
    float4* __restrict__ dst =
        (float4*)(out + base + (size_t)n * (size_t)D);
    int vecs = D >> 2;  // 64 for D=256
    #pragma unroll 2
    for (int j = lane; j < vecs; j += 32)
        dst[j] = src[j];
}

extern "C" void kernel_launch(void* const* d_in, const int* in_sizes, int n_in,
                              void* d_out, int out_size) {
    // Identify inputs by size, not position.
    int msg_i = 0;
    for (int i = 1; i < n_in; i++)
        if (in_sizes[i] > in_sizes[msg_i]) msg_i = i;

    int e_i[2] = {-1, -1};
    int c = 0;
    for (int i = 0; i < n_in && c < 2; i++)
        if (i != msg_i && in_sizes[i] > 1) e_i[c++] = i;

    const float* msg = (const float*)d_in[msg_i];
    const void*  pA  = d_in[e_i[0]];
    const void*  pB  = d_in[e_i[1]];
    float*       out = (float*)d_out;

    int E = in_sizes[e_i[0]];            // 1,000,000
    int D = in_sizes[msg_i] / E;         // 256

    // Prefer the all-f32 layout: uniq stored as float values.
    int N, uniq_i64;
    long long base;
    if (out_size % (D + 1) == 0) {       // f32 uniq + f32 rows (expected path)
        N = out_size / (D + 1);          // 100,000
        uniq_i64 = 0;
        base = (long long)N;
    } else {                             // fallback: int64 uniq + f32 rows
        N = out_size / (D + 2);
        uniq_i64 = 1;
        base = 2LL * N;
    }

    init_keys_kernel<<<(N + 255) / 256, 256>>>(out, base, N, D);
    scatter_max_kernel<<<(E + 255) / 256, 256>>>(pA, pB, out, base, E, N, D);
    gather_kernel<<<(N + 3) / 4, 128>>>(msg, out, base, N, D, E, uniq_i64);
}

// round 7
// speedup vs baseline: 1.0450x; 1.0450x over previous
#include <cuda_runtime.h>
#include <cstdint>

// Output (f32 elements): [ uniq as float 0..N-1 | msg rows f32 [N,D] ]
// Per-node best key (u64: t_bits<<32 | event_pos) lives in the FIRST 8 BYTES of
// output row n during scatter; the owning gather warp reads it then overwrites.
//
// K1: events i<N have index[i]=i (guaranteed) -> unique owner per slot: plain
//     store key(t[n],n). Doubles as the init (replaces stale data from the
//     previous graph replay).
// K2: events i in [N,E): atomicMax. PDL: loads run before griddepcontrol.wait.
// K3: gather; PDL: uniq writes (disjoint region) run before the wait.

__device__ __forceinline__ void pdl_wait() {
    asm volatile("griddepcontrol.wait;" ::: "memory");
}
__device__ __forceinline__ void pdl_release() {
    asm volatile("griddepcontrol.launch_dependents;" ::: "memory");
}

__device__ __forceinline__ unsigned long long*
key_slot(float* out, long long base, int D, int n) {
    return (unsigned long long*)(out + base + (size_t)n * (size_t)D);
}

// Which of pA/pB is t? index u32 words (arange prefix) are < N; uniform-[0,1)
// float bits (~0x3E000000+) are huge.
__device__ __forceinline__ const float*
pick_t(const void* pA, const void* pB, unsigned int nn) {
    const unsigned int* A32 = (const unsigned int*)pA;
    bool a_is_index = (A32[0] < nn) && (A32[2] < nn);
    return a_is_index ? (const float*)pB : (const float*)pA;
}

// K1: init + prefix scatter (one unique writer per slot, no atomics needed).
__global__ void __launch_bounds__(256)
prefix_keys_kernel(const void* __restrict__ pA, const void* __restrict__ pB,
                   float* __restrict__ out, long long base, int N, int D) {
    const float* __restrict__ t = pick_t(pA, pB, (unsigned int)N);
    int n = blockIdx.x * blockDim.x + threadIdx.x;
    if (n < N) {
        unsigned long long key =
            ((unsigned long long)__float_as_uint(t[n]) << 32) | (unsigned int)n;
        *key_slot(out, base, D, n) = key;
    }
    pdl_release();
}

// K2: remaining events, atomicMax. Input loads happen pre-wait (overlap K1).
__global__ void __launch_bounds__(256)
scatter_max_kernel(const void* __restrict__ pA, const void* __restrict__ pB,
                   float* __restrict__ out, long long base,
                   int E, int N, int D) {
    const unsigned int* A32 = (const unsigned int*)pA;
    unsigned int nn = (unsigned int)N;
    bool a_is_index = (A32[0] < nn) && (A32[2] < nn);
    const void* idxp = a_is_index ? pA : pB;
    const float* __restrict__ t =
        a_is_index ? (const float*)pB : (const float*)pA;
    // int64 index: odd u32 words of the arange prefix are 0; int32: 1,3,5.
    const unsigned int* I32 = (const unsigned int*)idxp;
    bool idx_is_i64 = (I32[1] == 0u) && (I32[3] == 0u) && (I32[5] == 0u);

    int i = N + blockIdx.x * blockDim.x + threadIdx.x;
    int id = 0;
    unsigned long long key = 0;
    bool active = (i < E);
    if (active) {
        id = idx_is_i64 ? (int)((const long long*)idxp)[i]
                        : ((const int*)idxp)[i];
        key = ((unsigned long long)__float_as_uint(t[i]) << 32) | (unsigned int)i;
        active = ((unsigned int)id < nn);
    }
    pdl_wait();                       // K1's stores now visible
    if (active)
        atomicMax(key_slot(out, base, D, id), key);
    pdl_release();
}

// K3: one warp per node row; 8 warps per block. uniq writes pre-wait.
__global__ void __launch_bounds__(256)
gather_kernel(const float* __restrict__ msg, float* __restrict__ out,
              long long base, int N, int D, int E, int uniq_i64) {
    int n = blockIdx.x * 8 + (threadIdx.x >> 5);
    int lane = threadIdx.x & 31;

    if (n < N && lane == 0) {         // disjoint from key slots: safe pre-wait
        if (uniq_i64) ((long long*)out)[n] = (long long)n;
        else          out[n] = (float)n;
    }
    pdl_wait();                       // all atomics done
    if (n >= N) return;

    unsigned long long key = *key_slot(out, base, D, n);   // broadcast load
    unsigned int pos = (unsigned int)(key & 0xFFFFFFFFULL);
    if (pos >= (unsigned int)E) pos = 0;                    // guard
    __syncwarp();   // every lane has the key before the row is overwritten

    const float4* __restrict__ src =
        (const float4*)(msg + (size_t)pos * (size_t)D);
    float4* __restrict__ dst =
        (float4*)(out + base + (size_t)n * (size_t)D);
    // D=256 -> 64 float4, exactly 2 per lane; issue both loads, then stores.
    if (D == 256) {
        float4 a = src[lane];
        float4 b = src[lane + 32];
        dst[lane]      = a;
        dst[lane + 32] = b;
    } else {
        int vecs = D >> 2;
        for (int j = lane; j < vecs; j += 32) dst[j] = src[j];
    }
}

template <typename... Args>
static inline void launch_pdl(void (*kern)(Args...), int grid, int block,
                              bool pdl, Args... args) {
    cudaLaunchConfig_t cfg = {};
    cfg.gridDim = dim3(grid);
    cfg.blockDim = dim3(block);
    cfg.dynamicSmemBytes = 0;
    cfg.stream = 0;
    cudaLaunchAttribute attr;
    attr.id = cudaLaunchAttributeProgrammaticStreamSerialization;
    attr.val.programmaticStreamSerializationAllowed = 1;
    cfg.attrs = pdl ? &attr : nullptr;
    cfg.numAttrs = pdl ? 1 : 0;
    cudaLaunchKernelEx(&cfg, kern, args...);
}

extern "C" void kernel_launch(void* const* d_in, const int* in_sizes, int n_in,
                              void* d_out, int out_size) {
    // Identify inputs by size, not position.
    int msg_i = 0;
    for (int i = 1; i < n_in; i++)
        if (in_sizes[i] > in_sizes[msg_i]) msg_i = i;
    int e_i[2] = {-1, -1};
    int c = 0;
    for (int i = 0; i < n_in && c < 2; i++)
        if (i != msg_i && in_sizes[i] > 1) e_i[c++] = i;

    const float* msg = (const float*)d_in[msg_i];
    const void*  pA  = d_in[e_i[0]];
    const void*  pB  = d_in[e_i[1]];
    float*       out = (float*)d_out;

    int E = in_sizes[e_i[0]];            // 1,000,000
    int D = in_sizes[msg_i] / E;         // 256

    int N, uniq_i64;
    long long base;
    if (out_size % (D + 1) == 0) {       // f32 uniq + f32 rows (live path)
        N = out_size / (D + 1);          // 100,000
        uniq_i64 = 0;
        base = (long long)N;
    } else {                             // fallback: int64 uniq
        N = out_size / (D + 2);
        uniq_i64 = 1;
        base = 2LL * N;
    }

    int rem = E - N;                     // events handled by atomic pass
    launch_pdl(prefix_keys_kernel, (N + 255) / 256, 256, false,
               pA, pB, out, base, N, D);
    launch_pdl(scatter_max_kernel, (rem + 255) / 256, 256, true,
               pA, pB, out, base, E, N, D);
    launch_pdl(gather_kernel, (N + 7) / 8, 256, true,
               msg, out, base, N, D, E, uniq_i64);
}